// round 9
// baseline (speedup 1.0000x reference)
#include <cuda_runtime.h>

// DCN CrossLayer closed form: out = x0 * a3 + (b0+b1+b2), with
//   d_l = dot(x0, w_l), c1 = dot(b0,w1), c2 = dot(b0+b1,w2),
//   a1 = 1+d0; s1 = a1*d1+c1; a2 = a1+s1; s2 = a2*d2+c2; a3 = a2+s2.
//
// Warp-per-2-rows, no persistent x registers (epilogue reloads x, L1/L2 hot).
// One streamed pass over w serves both rows' 3 dots; one batched 8-SHFL
// butterfly reduces all 6 partials. Single __syncthreads (prologue only).

#define F_DIM 1024
#define F4    256
#define FULL  0xffffffffu

__device__ __forceinline__ float dot4(float4 a, float4 b, float acc) {
    acc = fmaf(a.x, b.x, acc);
    acc = fmaf(a.y, b.y, acc);
    acc = fmaf(a.z, b.z, acc);
    return fmaf(a.w, b.w, acc);
}

// Pairing step: merges two independent reductions one level deeper.
// Lanes with (lane&off)==0 carry 'a', others carry 'b'.
__device__ __forceinline__ float pair_step(float a, float b, int off, int lane) {
    const bool hi = (lane & off) != 0;
    float keep = hi ? b : a;
    float send = hi ? a : b;
    return keep + __shfl_xor_sync(FULL, send, off);
}

__global__ void __launch_bounds__(256, 5)
cross_layer_kernel(const float4* __restrict__ x,
                   const float*  __restrict__ w,   // [3,1024]
                   const float*  __restrict__ b,   // [3,1024]
                   float4* __restrict__ out)
{
    __shared__ float4 sB[F4];     // b0+b1+b2 per feature chunk
    __shared__ float2 sC[8];      // (c1,c2) warp partials

    const int tid  = threadIdx.x;
    const int lane = tid & 31;
    const int wid  = tid >> 5;

    // ---- Prologue: B into smem, c1/c2 block scalars. ONE sync. ----
    {
        const float4 w1v = __ldg(&((const float4*)(w + F_DIM))[tid]);
        const float4 w2v = __ldg(&((const float4*)(w + 2 * F_DIM))[tid]);
        const float4 b0v = __ldg(&((const float4*)(b))[tid]);
        const float4 b1v = __ldg(&((const float4*)(b + F_DIM))[tid]);
        const float4 b2v = __ldg(&((const float4*)(b + 2 * F_DIM))[tid]);

        float4 b01, B;
        b01.x = b0v.x + b1v.x;  b01.y = b0v.y + b1v.y;
        b01.z = b0v.z + b1v.z;  b01.w = b0v.w + b1v.w;
        B.x = b01.x + b2v.x;    B.y = b01.y + b2v.y;
        B.z = b01.z + b2v.z;    B.w = b01.w + b2v.w;
        sB[tid] = B;

        float q = pair_step(dot4(b0v, w1v, 0.0f), dot4(b01, w2v, 0.0f), 16, lane);
#pragma unroll
        for (int o = 8; o; o >>= 1) q += __shfl_xor_sync(FULL, q, o);
        if (lane == 0)  sC[wid].x = q;
        if (lane == 16) sC[wid].y = q;
    }
    __syncthreads();

    float c1 = 0.0f, c2 = 0.0f;
#pragma unroll
    for (int i = 0; i < 8; i++) { float2 v = sC[i]; c1 += v.x; c2 += v.y; }

    // ---- Warp handles two adjacent rows; no further synchronization. ----
    const int rowA = blockIdx.x * 16 + wid * 2;
    const float4* __restrict__ xa = x + (size_t)rowA * F4;
    const float4* __restrict__ xb = xa + F4;

    const float4* __restrict__ w0g = (const float4*)(w);
    const float4* __restrict__ w1g = (const float4*)(w + F_DIM);
    const float4* __restrict__ w2g = (const float4*)(w + 2 * F_DIM);

    // Streamed pass: 6 dot-partials, one traversal of w.
    float p0a = 0.0f, p1a = 0.0f, p2a = 0.0f;
    float p0b = 0.0f, p1b = 0.0f, p2b = 0.0f;
#pragma unroll
    for (int i = 0; i < 8; i++) {
        const int idx = i * 32 + lane;
        const float4 va  = __ldg(&xa[idx]);
        const float4 vb  = __ldg(&xb[idx]);
        const float4 w0v = __ldg(&w0g[idx]);
        const float4 w1v = __ldg(&w1g[idx]);
        const float4 w2v = __ldg(&w2g[idx]);
        p0a = dot4(va, w0v, p0a);
        p1a = dot4(va, w1v, p1a);
        p2a = dot4(va, w2v, p2a);
        p0b = dot4(vb, w0v, p0b);
        p1b = dot4(vb, w1v, p1b);
        p2b = dot4(vb, w2v, p2b);
    }

    // Batched butterfly: 8 SHFLs reduce all 6 scalars.
    // Level 16: u0 = {p0a|p1a}, u1 = {p2a|p0b}, u2 = {p1b|p2b}
    float u0 = pair_step(p0a, p1a, 16, lane);
    float u1 = pair_step(p2a, p0b, 16, lane);
    float u2 = pair_step(p1b, p2b, 16, lane);
    // Level 8: t0 = {u0|u1}, t1 = u2 (self-reduced over bit3)
    float t0 = pair_step(u0, u1, 8, lane);
    float t1 = u2 + __shfl_xor_sync(FULL, u2, 8);
    // Level 4: s = {t0|t1}; then full reduce bits 1,0.
    float q = pair_step(t0, t1, 4, lane);
    q += __shfl_xor_sync(FULL, q, 2);
    q += __shfl_xor_sync(FULL, q, 1);

    // id(lane): b2=0 -> (b3=0 ? (b4 ? d1a : d0a) : (b4 ? d0b : d2a))
    //           b2=1 -> (b4 ? d2b : d1b)
    const float d0a = __shfl_sync(FULL, q, 0);
    const float d1a = __shfl_sync(FULL, q, 16);
    const float d2a = __shfl_sync(FULL, q, 8);
    const float d0b = __shfl_sync(FULL, q, 24);
    const float d1b = __shfl_sync(FULL, q, 4);
    const float d2b = __shfl_sync(FULL, q, 20);

    const float a1A = 1.0f + d0a;
    const float s1A = fmaf(a1A, d1a, c1);
    const float a2A = a1A + s1A;
    const float s2A = fmaf(a2A, d2a, c2);
    const float a3A = a2A + s2A;

    const float a1B = 1.0f + d0b;
    const float s1B = fmaf(a1B, d1b, c1);
    const float a2B = a1B + s1B;
    const float s2B = fmaf(a2B, d2b, c2);
    const float a3B = a2B + s2B;

    // Epilogue: reload x (L1/L2 hit), out = x0 * a3 + B.
    float4* __restrict__ oa = out + (size_t)rowA * F4;
    float4* __restrict__ ob = oa + F4;
#pragma unroll
    for (int i = 0; i < 8; i++) {
        const int idx = i * 32 + lane;
        const float4 va = __ldg(&xa[idx]);
        const float4 vb = __ldg(&xb[idx]);
        const float4 Bv = sB[idx];
        float4 ra, rb;
        ra.x = fmaf(va.x, a3A, Bv.x);  ra.y = fmaf(va.y, a3A, Bv.y);
        ra.z = fmaf(va.z, a3A, Bv.z);  ra.w = fmaf(va.w, a3A, Bv.w);
        rb.x = fmaf(vb.x, a3B, Bv.x);  rb.y = fmaf(vb.y, a3B, Bv.y);
        rb.z = fmaf(vb.z, a3B, Bv.z);  rb.w = fmaf(vb.w, a3B, Bv.w);
        oa[idx] = ra;
        ob[idx] = rb;
    }
}

extern "C" void kernel_launch(void* const* d_in, const int* in_sizes, int n_in,
                              void* d_out, int out_size)
{
    const float4* x = (const float4*)d_in[0];
    const float*  w = (const float*)d_in[1];   // [3,1024,1]
    const float*  b = (const float*)d_in[2];   // [3,1024,1]
    float4* out = (float4*)d_out;

    const int n_rows = in_sizes[0] / F_DIM;    // 16384
    const int grid   = n_rows / 16;            // 8 warps x 2 rows per block

    cross_layer_kernel<<<grid, 256>>>(x, w, b, out);
}

// round 10
// speedup vs baseline: 1.8441x; 1.8441x over previous
#include <cuda_runtime.h>

// DCN CrossLayer closed form: out = x0 * a3 + (b0+b1+b2), with
//   d_l = dot(x0, w_l), c1 = dot(b0,w1), c2 = dot(b0+b1,w2),
//   a1 = 1+d0; s1 = a1*d1+c1; a2 = a1+s1; s2 = a2*d2+c2; a3 = a2+s2.
//
// Thread-owns-feature: 256 threads, thread t owns float4 chunk t of F=1024.
// w0/w1/w2 register-resident; B in smem. 4 rows per phase, 2 phases.
// 12 warp reductions in ONE batched 13-SHFL pairing butterfly.
// Stage-2 combine done redundantly per-warp (no serializing warp-0 stage,
// no extra sync). Partials smem double-buffered. x retained in registers
// (reloads provably miss L2 -> DRAM).

#define F_DIM 1024
#define F4    256
#define RPI   4
#define ROWS_PER_BLOCK 8
#define FULL  0xffffffffu

__device__ __forceinline__ float dot4(float4 a, float4 b) {
    float acc = a.x * b.x;
    acc = fmaf(a.y, b.y, acc);
    acc = fmaf(a.z, b.z, acc);
    return fmaf(a.w, b.w, acc);
}

// Pairing step: merges two independent reductions one level deeper.
__device__ __forceinline__ float pair_step(float a, float b, int off, int lane) {
    const bool hi = (lane & off) != 0;
    float keep = hi ? b : a;
    float send = hi ? a : b;
    return keep + __shfl_xor_sync(FULL, send, off);
}

__global__ void __launch_bounds__(256, 5)
cross_layer_kernel(const float4* __restrict__ x,
                   const float*  __restrict__ w,   // [3,1024]
                   const float*  __restrict__ b,   // [3,1024]
                   float4* __restrict__ out)
{
    __shared__ float  sPf[2][12 * 8];  // [phase-parity][sum_id][warp]
    __shared__ float4 sB[F4];          // b0+b1+b2 per feature chunk
    __shared__ float2 sC[8];           // (c1,c2) warp partials

    const int tid  = threadIdx.x;
    const int lane = tid & 31;
    const int wid  = tid >> 5;

    // ---- Register-resident weights at this thread's feature chunk ----
    const float4 w0 = __ldg(&((const float4*)(w))[tid]);
    const float4 w1 = __ldg(&((const float4*)(w + F_DIM))[tid]);
    const float4 w2 = __ldg(&((const float4*)(w + 2 * F_DIM))[tid]);

    // ---- Prologue: B -> smem, c1/c2 block scalars. ----
    {
        const float4 b0v = __ldg(&((const float4*)(b))[tid]);
        const float4 b1v = __ldg(&((const float4*)(b + F_DIM))[tid]);
        const float4 b2v = __ldg(&((const float4*)(b + 2 * F_DIM))[tid]);
        float4 b01, B;
        b01.x = b0v.x + b1v.x;  b01.y = b0v.y + b1v.y;
        b01.z = b0v.z + b1v.z;  b01.w = b0v.w + b1v.w;
        B.x = b01.x + b2v.x;    B.y = b01.y + b2v.y;
        B.z = b01.z + b2v.z;    B.w = b01.w + b2v.w;
        sB[tid] = B;

        float q = pair_step(dot4(b0v, w1), dot4(b01, w2), 16, lane);
#pragma unroll
        for (int o = 8; o; o >>= 1) q += __shfl_xor_sync(FULL, q, o);
        if (lane == 0)  sC[wid].x = q;
        if (lane == 16) sC[wid].y = q;
    }
    __syncthreads();

    float c1 = 0.0f, c2 = 0.0f;
#pragma unroll
    for (int i = 0; i < 8; i++) { float2 v = sC[i]; c1 += v.x; c2 += v.y; }

    const size_t base = (size_t)blockIdx.x * ROWS_PER_BLOCK * F4 + tid;
    const float4* __restrict__ xp = x + base;
    float4*       __restrict__ op = out + base;

#pragma unroll
    for (int it = 0; it < 2; it++) {
        float* __restrict__ sP = sPf[it];

        // Front-batched loads: 4 independent LDG.128 per thread.
        float4 xr[RPI];
#pragma unroll
        for (int r = 0; r < RPI; r++)
            xr[r] = __ldg(xp + (it * RPI + r) * F4);

        // 12 per-thread partials (3 dots x 4 rows).
        float p[12];
#pragma unroll
        for (int r = 0; r < RPI; r++) {
            p[3 * r + 0] = dot4(xr[r], w0);
            p[3 * r + 1] = dot4(xr[r], w1);
            p[3 * r + 2] = dot4(xr[r], w2);
        }

        // Batched butterfly: 13 SHFLs reduce all 12 scalars (verified R6).
        float u0 = pair_step(p[0],  p[1],  16, lane);
        float u1 = pair_step(p[2],  p[3],  16, lane);
        float u2 = pair_step(p[4],  p[5],  16, lane);
        float u3 = pair_step(p[6],  p[7],  16, lane);
        float u4 = pair_step(p[8],  p[9],  16, lane);
        float u5 = pair_step(p[10], p[11], 16, lane);
        float t0 = pair_step(u0, u1, 8, lane);
        float t1 = pair_step(u2, u3, 8, lane);
        float t2 = pair_step(u4, u5, 8, lane);
        float s0 = pair_step(t0, t1, 4, lane);
        float s1 = t2 + __shfl_xor_sync(FULL, t2, 4);
        float q  = pair_step(s0, s1, 2, lane);
        q += __shfl_xor_sync(FULL, q, 1);

        // Lane -> sum_id mapping (verified R6):
        //   b1==0: id = 4*b2 + 2*b3 + b4 ; b1==1: id = 8 + 2*b3 + b4
        const int b4 = (lane >> 4) & 1, b3 = (lane >> 3) & 1;
        const int b2i = (lane >> 2) & 1, b1i = (lane >> 1) & 1, b0v = lane & 1;
        const int  id     = b1i ? (8 + 2 * b3 + b4) : (4 * b2i + 2 * b3 + b4);
        const bool writer = (b0v == 0) && (b1i == 0 || b2i == 0);
        if (writer) sP[id * 8 + wid] = q;
        __syncthreads();

        // Per-warp stage-2: lanes 0..11 sum the 8 warp-partials of their id.
        float dsum = 0.0f;
        if (lane < 12) {
            const float4* pp = (const float4*)(sP + lane * 8);
            float4 aa = pp[0], bb = pp[1];
            dsum = ((aa.x + aa.y) + (aa.z + aa.w))
                 + ((bb.x + bb.y) + (bb.z + bb.w));
        }

        // Broadcast and finish a3 for each of the 4 rows (all lanes).
        float a3r[RPI];
#pragma unroll
        for (int r = 0; r < RPI; r++) {
            const float d0 = __shfl_sync(FULL, dsum, 3 * r + 0);
            const float d1 = __shfl_sync(FULL, dsum, 3 * r + 1);
            const float d2 = __shfl_sync(FULL, dsum, 3 * r + 2);
            const float a1v = 1.0f + d0;
            const float s1v = fmaf(a1v, d1, c1);
            const float a2v = a1v + s1v;
            const float s2v = fmaf(a2v, d2, c2);
            a3r[r] = a2v + s2v;
        }

        // Epilogue: out = x0 * a3 + B.
        const float4 Bv = sB[tid];
#pragma unroll
        for (int r = 0; r < RPI; r++) {
            float4 o;
            o.x = fmaf(xr[r].x, a3r[r], Bv.x);
            o.y = fmaf(xr[r].y, a3r[r], Bv.y);
            o.z = fmaf(xr[r].z, a3r[r], Bv.z);
            o.w = fmaf(xr[r].w, a3r[r], Bv.w);
            op[(it * RPI + r) * F4] = o;
        }
    }
}

extern "C" void kernel_launch(void* const* d_in, const int* in_sizes, int n_in,
                              void* d_out, int out_size)
{
    const float4* x = (const float4*)d_in[0];
    const float*  w = (const float*)d_in[1];   // [3,1024,1]
    const float*  b = (const float*)d_in[2];   // [3,1024,1]
    float4* out = (float4*)d_out;

    const int n_rows = in_sizes[0] / F_DIM;                           // 16384
    const int grid   = (n_rows + ROWS_PER_BLOCK - 1) / ROWS_PER_BLOCK; // 2048

    cross_layer_kernel<<<grid, 256>>>(x, w, b, out);
}